// round 4
// baseline (speedup 1.0000x reference)
#include <cuda_runtime.h>

#define VOCAB 10000
#define EMBED 300
#define BATCH 262144

#define NBLOCKS 2048
#define NTHREADS 256
#define GROUPS_PER_BLOCK (NTHREADS / 8)            // 32 eight-lane groups
#define TOTAL_GROUPS (NBLOCKS * GROUPS_PER_BLOCK)  // 65536
#define PAIRS_PER_GROUP (BATCH / TOTAL_GROUPS)     // 4 consecutive pairs per group

// Scratch (static __device__ arrays: allowed; zero-initialized at load).
__device__ int          g_hist[VOCAB];      // re-zeroed by scan kernel each run
__device__ int          g_offsets[VOCAB];
__device__ int          g_si[BATCH];
__device__ int          g_sj[BATCH];
__device__ float        g_partials[NBLOCKS];
__device__ unsigned int g_count = 0;        // self-resets each run

// ---------------- Pass 1: histogram of center indices ----------------
__global__ void glove_hist_kernel(const int* __restrict__ ci) {
    int p = blockIdx.x * blockDim.x + threadIdx.x;
    if (p < BATCH) atomicAdd(&g_hist[ci[p]], 1);
}

// ---------------- Pass 2: exclusive scan (1 block); re-zero hist ----------------
__global__ void __launch_bounds__(256) glove_scan_kernel() {
    __shared__ int ssum[256];
    const int t = threadIdx.x;
    const int base = t * 40;                 // 256*40 = 10240 >= VOCAB

    int s = 0;
    for (int k = 0; k < 40; k++) {
        int idx = base + k;
        if (idx < VOCAB) s += g_hist[idx];
    }
    ssum[t] = s;
    __syncthreads();
    if (t == 0) {
        int acc = 0;
        for (int k = 0; k < 256; k++) { int v = ssum[k]; ssum[k] = acc; acc += v; }
    }
    __syncthreads();
    int off = ssum[t];
    for (int k = 0; k < 40; k++) {
        int idx = base + k;
        if (idx < VOCAB) {
            int v = g_hist[idx];
            g_offsets[idx] = off;
            off += v;
            g_hist[idx] = 0;                 // ready for next graph replay
        }
    }
}

// ---------------- Pass 3: scatter pairs into i-sorted order ----------------
__global__ void glove_scatter_kernel(const int* __restrict__ ci,
                                     const int* __restrict__ cj) {
    int p = blockIdx.x * blockDim.x + threadIdx.x;
    if (p < BATCH) {
        int i = ci[p];
        int j = cj[p];
        int pos = atomicAdd(&g_offsets[i], 1);
        g_si[pos] = i;
        g_sj[pos] = j;
    }
}

// ---------------- Pass 4: fused gather + dot + loss + reduce ----------------
__global__ void __launch_bounds__(NTHREADS)
glove_main_kernel(const float* __restrict__ V,
                  const float* __restrict__ U,
                  const float* __restrict__ vb,
                  const float* __restrict__ ub,
                  const float* __restrict__ comat,
                  float* __restrict__ out) {
    const int lane = threadIdx.x & 31;
    const int sub  = lane & 7;               // lane within 8-lane group
    const int wid  = threadIdx.x >> 5;
    const int group = blockIdx.x * GROUPS_PER_BLOCK + (threadIdx.x >> 3);
    const int pbase = group * PAIRS_PER_GROUP;

    float  gsum = 0.0f;                      // only sub==0 lanes accumulate
    int    prev_i = -1;
    float4 va[10];                           // register-cached V row slice

    #pragma unroll
    for (int q = 0; q < PAIRS_PER_GROUP; q++) {
        const int p = pbase + q;
        const int i = g_si[p];
        const int j = g_sj[p];

        if (i != prev_i) {
            const float4* __restrict__ v4 = (const float4*)(V + (size_t)i * EMBED);
            #pragma unroll
            for (int k = 0; k < 9; k++) va[k] = __ldg(v4 + sub + k * 8);
            if (sub < 3) va[9] = __ldg(v4 + sub + 72);
            prev_i = i;
        }

        const float4* __restrict__ u4 = (const float4*)(U + (size_t)j * EMBED);
        float acc = 0.0f;
        #pragma unroll
        for (int k = 0; k < 9; k++) {
            float4 b = __ldg(u4 + sub + k * 8);
            acc += va[k].x * b.x + va[k].y * b.y + va[k].z * b.z + va[k].w * b.w;
        }
        if (sub < 3) {
            float4 b = __ldg(u4 + sub + 72);
            acc += va[9].x * b.x + va[9].y * b.y + va[9].z * b.z + va[9].w * b.w;
        }

        // reduce within the 8-lane group
        acc += __shfl_xor_sync(0xffffffffu, acc, 4);
        acc += __shfl_xor_sync(0xffffffffu, acc, 2);
        acc += __shfl_xor_sync(0xffffffffu, acc, 1);

        if (sub == 0) {
            float x = __ldg(comat + (size_t)i * VOCAB + j);
            float w = (x < 100.0f) ? __powf(x * 0.01f, 0.75f) : 1.0f;
            float r = acc + __ldg(vb + i) + __ldg(ub + j) - __logf(x);
            gsum += w * r * r;
        }
    }

    // warp reduce: nonzero only on lanes 0,8,16,24
    gsum += __shfl_xor_sync(0xffffffffu, gsum, 8);
    gsum += __shfl_xor_sync(0xffffffffu, gsum, 16);

    __shared__ float swsum[NTHREADS / 32];
    __shared__ bool  s_last;
    if (lane == 0) swsum[wid] = gsum;
    __syncthreads();

    if (threadIdx.x == 0) {
        float bsum = 0.0f;
        #pragma unroll
        for (int w = 0; w < NTHREADS / 32; w++) bsum += swsum[w];
        g_partials[blockIdx.x] = bsum;
        __threadfence();
        unsigned int t = atomicAdd(&g_count, 1u);
        s_last = (t == (unsigned int)(gridDim.x - 1));
    }
    __syncthreads();

    if (s_last) {
        double d = 0.0;
        for (int k = threadIdx.x; k < NBLOCKS; k += NTHREADS)
            d += (double)g_partials[k];
        #pragma unroll
        for (int off = 16; off; off >>= 1)
            d += __shfl_xor_sync(0xffffffffu, d, off);

        __shared__ double sdw[NTHREADS / 32];
        if (lane == 0) sdw[wid] = d;
        __syncthreads();
        if (threadIdx.x == 0) {
            double total = 0.0;
            #pragma unroll
            for (int w = 0; w < NTHREADS / 32; w++) total += sdw[w];
            out[0] = (float)total;
            g_count = 0;                     // reset for next graph replay
        }
    }
}

extern "C" void kernel_launch(void* const* d_in, const int* in_sizes, int n_in,
                              void* d_out, int out_size) {
    const int*   ci    = (const int*)d_in[0];
    const int*   cj    = (const int*)d_in[1];
    const float* V     = (const float*)d_in[2];
    const float* U     = (const float*)d_in[3];
    const float* vb    = (const float*)d_in[4];
    const float* ub    = (const float*)d_in[5];
    const float* comat = (const float*)d_in[6];
    float* out = (float*)d_out;

    glove_hist_kernel<<<(BATCH + 255) / 256, 256>>>(ci);
    glove_scan_kernel<<<1, 256>>>();
    glove_scatter_kernel<<<(BATCH + 255) / 256, 256>>>(ci, cj);
    glove_main_kernel<<<NBLOCKS, NTHREADS>>>(V, U, vb, ub, comat, out);
}

// round 5
// speedup vs baseline: 1.0906x; 1.0906x over previous
#include <cuda_runtime.h>

#define VOCAB 10000
#define EMBED 300
#define BATCH 262144

#define NBLOCKS 2048
#define NTHREADS 256
#define GROUPS_PER_BLOCK (NTHREADS / 8)            // 32 eight-lane groups
#define TOTAL_GROUPS (NBLOCKS * GROUPS_PER_BLOCK)  // 65536
#define PAIRS_PER_GROUP (BATCH / TOTAL_GROUPS)     // 4 consecutive sorted pairs/group

// Scratch (__device__ globals: allowed; zero-initialized at load).
__device__ int          g_hist[VOCAB];      // re-zeroed by scan kernel each run
__device__ int          g_offsets[VOCAB];
__device__ int          g_si[BATCH];
__device__ int          g_sj[BATCH];
__device__ float        g_partials[NBLOCKS];
__device__ unsigned int g_count = 0;        // self-resets each run

// ---------------- Pass 1: histogram of center indices ----------------
__global__ void glove_hist_kernel(const int* __restrict__ ci) {
    int p = blockIdx.x * blockDim.x + threadIdx.x;
    if (p < BATCH) atomicAdd(&g_hist[ci[p]], 1);
}

// ---------------- Pass 2: parallel exclusive scan (1 block); re-zero hist ----
#define BINS_PER_THREAD 40                   // 256*40 = 10240 >= VOCAB
__global__ void __launch_bounds__(256) glove_scan_kernel() {
    const int t    = threadIdx.x;
    const int lane = t & 31;
    const int wid  = t >> 5;
    const int base = t * BINS_PER_THREAD;

    // per-thread bin-range sum
    int s = 0;
    #pragma unroll 8
    for (int k = 0; k < BINS_PER_THREAD; k++) {
        int idx = base + k;
        if (idx < VOCAB) s += g_hist[idx];
    }

    // warp inclusive scan (shfl)
    int incl = s;
    #pragma unroll
    for (int d = 1; d < 32; d <<= 1) {
        int v = __shfl_up_sync(0xffffffffu, incl, d);
        if (lane >= d) incl += v;
    }

    __shared__ int wsum[8];
    if (lane == 31) wsum[wid] = incl;
    __syncthreads();
    if (t < 8) {
        int v = wsum[t];
        int e = 0;
        #pragma unroll
        for (int d = 1; d < 8; d <<= 1) {
            int u = __shfl_up_sync(0x000000ffu, v, d);
            if (t >= d) v += u;
        }
        e = v - wsum[t];                     // exclusive warp offsets
        wsum[t] = e;
    }
    __syncthreads();

    int off = wsum[wid] + (incl - s);        // exclusive prefix for this thread

    #pragma unroll 8
    for (int k = 0; k < BINS_PER_THREAD; k++) {
        int idx = base + k;
        if (idx < VOCAB) {
            int v = g_hist[idx];
            g_offsets[idx] = off;
            off += v;
            g_hist[idx] = 0;                 // ready for next graph replay
        }
    }
}

// ---------------- Pass 3: scatter pairs into i-sorted order ----------------
__global__ void glove_scatter_kernel(const int* __restrict__ ci,
                                     const int* __restrict__ cj) {
    int p = blockIdx.x * blockDim.x + threadIdx.x;
    if (p < BATCH) {
        int i = ci[p];
        int j = cj[p];
        int pos = atomicAdd(&g_offsets[i], 1);
        g_si[pos] = i;
        g_sj[pos] = j;
    }
}

// ---------------- Pass 4: fused gather + dot + loss + reduce ----------------
__global__ void __launch_bounds__(NTHREADS)
glove_main_kernel(const float* __restrict__ V,
                  const float* __restrict__ U,
                  const float* __restrict__ vb,
                  const float* __restrict__ ub,
                  const float* __restrict__ comat,
                  float* __restrict__ out) {
    const int lane = threadIdx.x & 31;
    const int sub  = lane & 7;               // lane within 8-lane group
    const int wid  = threadIdx.x >> 5;
    const int group = blockIdx.x * GROUPS_PER_BLOCK + (threadIdx.x >> 3);
    const int pbase = group * PAIRS_PER_GROUP;

    float gsum = 0.0f;                       // only sub==0 lanes accumulate

    #pragma unroll
    for (int q = 0; q < PAIRS_PER_GROUP; q++) {
        const int p = pbase + q;
        const int i = g_si[p];
        const int j = g_sj[p];

        // Sorted by i: V row hits L1 on all but the first touch.
        const float4* __restrict__ v4 = (const float4*)(V + (size_t)i * EMBED);
        const float4* __restrict__ u4 = (const float4*)(U + (size_t)j * EMBED);

        float acc = 0.0f;
        #pragma unroll
        for (int k = 0; k < 9; k++) {
            float4 a = __ldg(v4 + sub + k * 8);
            float4 b = __ldg(u4 + sub + k * 8);
            acc += a.x * b.x + a.y * b.y + a.z * b.z + a.w * b.w;
        }
        if (sub < 3) {
            float4 a = __ldg(v4 + sub + 72);
            float4 b = __ldg(u4 + sub + 72);
            acc += a.x * b.x + a.y * b.y + a.z * b.z + a.w * b.w;
        }

        // reduce within the 8-lane group
        acc += __shfl_xor_sync(0xffffffffu, acc, 4);
        acc += __shfl_xor_sync(0xffffffffu, acc, 2);
        acc += __shfl_xor_sync(0xffffffffu, acc, 1);

        if (sub == 0) {
            float x = __ldg(comat + (size_t)i * VOCAB + j);
            float w = (x < 100.0f) ? __powf(x * 0.01f, 0.75f) : 1.0f;
            float r = acc + __ldg(vb + i) + __ldg(ub + j) - __logf(x);
            gsum += w * r * r;
        }
    }

    // warp reduce: nonzero only on lanes 0,8,16,24
    gsum += __shfl_xor_sync(0xffffffffu, gsum, 8);
    gsum += __shfl_xor_sync(0xffffffffu, gsum, 16);

    __shared__ float swsum[NTHREADS / 32];
    __shared__ bool  s_last;
    if (lane == 0) swsum[wid] = gsum;
    __syncthreads();

    if (threadIdx.x == 0) {
        float bsum = 0.0f;
        #pragma unroll
        for (int w = 0; w < NTHREADS / 32; w++) bsum += swsum[w];
        g_partials[blockIdx.x] = bsum;
        __threadfence();
        unsigned int t = atomicAdd(&g_count, 1u);
        s_last = (t == (unsigned int)(gridDim.x - 1));
    }
    __syncthreads();

    if (s_last) {
        double d = 0.0;
        for (int k = threadIdx.x; k < NBLOCKS; k += NTHREADS)
            d += (double)g_partials[k];
        #pragma unroll
        for (int off = 16; off; off >>= 1)
            d += __shfl_xor_sync(0xffffffffu, d, off);

        __shared__ double sdw[NTHREADS / 32];
        if (lane == 0) sdw[wid] = d;
        __syncthreads();
        if (threadIdx.x == 0) {
            double total = 0.0;
            #pragma unroll
            for (int w = 0; w < NTHREADS / 32; w++) total += sdw[w];
            out[0] = (float)total;
            g_count = 0;                     // reset for next graph replay
        }
    }
}

extern "C" void kernel_launch(void* const* d_in, const int* in_sizes, int n_in,
                              void* d_out, int out_size) {
    const int*   ci    = (const int*)d_in[0];
    const int*   cj    = (const int*)d_in[1];
    const float* V     = (const float*)d_in[2];
    const float* U     = (const float*)d_in[3];
    const float* vb    = (const float*)d_in[4];
    const float* ub    = (const float*)d_in[5];
    const float* comat = (const float*)d_in[6];
    float* out = (float*)d_out;

    glove_hist_kernel<<<(BATCH + 255) / 256, 256>>>(ci);
    glove_scan_kernel<<<1, 256>>>();
    glove_scatter_kernel<<<(BATCH + 255) / 256, 256>>>(ci, cj);
    glove_main_kernel<<<NBLOCKS, NTHREADS>>>(V, U, vb, ub, comat, out);
}

// round 6
// speedup vs baseline: 1.8131x; 1.6625x over previous
#include <cuda_runtime.h>
#include <cuda_fp16.h>

#define VOCAB 10000
#define EMBED 300
#define BATCH 262144

#define ROW_H2 160                                  // padded row stride in half2 (320 halves)
#define ROW_U4 40                                   // 40 uint4 per padded row
#define H2_PER_ROW 150                              // real half2 per row

#define NBLOCKS 2048
#define NTHREADS 256
#define GROUPS_PER_BLOCK (NTHREADS / 8)             // 32 eight-lane groups
#define TOTAL_GROUPS (NBLOCKS * GROUPS_PER_BLOCK)   // 65536
#define PAIRS_PER_GROUP (BATCH / TOTAL_GROUPS)      // 4

// fp16 copies of V and U (zero-initialized at load; pad columns 150..159 never
// written, so they stay zero and contribute nothing to the dots).
__device__ __half2       g_Vh[VOCAB * ROW_H2];
__device__ __half2       g_Uh[VOCAB * ROW_H2];
__device__ float         g_partials[NBLOCKS];
__device__ unsigned int  g_count = 0;               // self-resets each run

// ---------------- Pass 1: fp32 -> fp16 conversion (streaming) ----------------
__global__ void glove_conv_kernel(const float* __restrict__ V,
                                  const float* __restrict__ U) {
    const int PER = VOCAB * H2_PER_ROW;             // 1.5M half2 per matrix
    int t = blockIdx.x * blockDim.x + threadIdx.x;
    if (t < PER) {
        int row = t / H2_PER_ROW;
        int c   = t - row * H2_PER_ROW;
        float2 f = ((const float2*)(V + (size_t)row * EMBED))[c];
        g_Vh[row * ROW_H2 + c] = __floats2half2_rn(f.x, f.y);
    } else if (t < 2 * PER) {
        int s   = t - PER;
        int row = s / H2_PER_ROW;
        int c   = s - row * H2_PER_ROW;
        float2 f = ((const float2*)(U + (size_t)row * EMBED))[c];
        g_Uh[row * ROW_H2 + c] = __floats2half2_rn(f.x, f.y);
    }
}

// ---------------- Pass 2: fused gather + dot + loss + reduce ----------------
__global__ void __launch_bounds__(NTHREADS)
glove_main_kernel(const int* __restrict__ ci,
                  const int* __restrict__ cj,
                  const float* __restrict__ vb,
                  const float* __restrict__ ub,
                  const float* __restrict__ comat,
                  float* __restrict__ out) {
    const int lane = threadIdx.x & 31;
    const int sub  = lane & 7;                      // lane within 8-lane group
    const int wid  = threadIdx.x >> 5;
    const int group = blockIdx.x * GROUPS_PER_BLOCK + (threadIdx.x >> 3);

    float gsum = 0.0f;                              // only sub==0 lanes accumulate

    #pragma unroll
    for (int q = 0; q < PAIRS_PER_GROUP; q++) {
        const int p = group + q * TOTAL_GROUPS;     // coalesced index reads
        const int i = ci[p];
        const int j = cj[p];

        const uint4* __restrict__ v4 = (const uint4*)(g_Vh + (size_t)i * ROW_H2);
        const uint4* __restrict__ u4 = (const uint4*)(g_Uh + (size_t)j * ROW_H2);

        // 40 uint4 (=320 halves incl. zero pad) per row; 8 lanes x 5 rounds.
        float acc = 0.0f;
        #pragma unroll
        for (int k = 0; k < 5; k++) {
            uint4 a = v4[sub + k * 8];
            uint4 b = u4[sub + k * 8];
            const __half2* ah = (const __half2*)&a;
            const __half2* bh = (const __half2*)&b;
            #pragma unroll
            for (int m = 0; m < 4; m++) {
                float2 af = __half22float2(ah[m]);
                float2 bf = __half22float2(bh[m]);
                acc = fmaf(af.x, bf.x, acc);
                acc = fmaf(af.y, bf.y, acc);
            }
        }

        // reduce within the 8-lane group
        acc += __shfl_xor_sync(0xffffffffu, acc, 4);
        acc += __shfl_xor_sync(0xffffffffu, acc, 2);
        acc += __shfl_xor_sync(0xffffffffu, acc, 1);

        if (sub == 0) {
            float x = __ldg(comat + (size_t)i * VOCAB + j);
            float w = (x < 100.0f) ? __powf(x * 0.01f, 0.75f) : 1.0f;
            float r = acc + __ldg(vb + i) + __ldg(ub + j) - __logf(x);
            gsum += w * r * r;
        }
    }

    // warp reduce: nonzero only on lanes 0,8,16,24
    gsum += __shfl_xor_sync(0xffffffffu, gsum, 8);
    gsum += __shfl_xor_sync(0xffffffffu, gsum, 16);

    __shared__ float swsum[NTHREADS / 32];
    __shared__ bool  s_last;
    if (lane == 0) swsum[wid] = gsum;
    __syncthreads();

    if (threadIdx.x == 0) {
        float bsum = 0.0f;
        #pragma unroll
        for (int w = 0; w < NTHREADS / 32; w++) bsum += swsum[w];
        g_partials[blockIdx.x] = bsum;
        __threadfence();
        unsigned int t = atomicAdd(&g_count, 1u);
        s_last = (t == (unsigned int)(gridDim.x - 1));
    }
    __syncthreads();

    if (s_last) {
        double d = 0.0;
        for (int k = threadIdx.x; k < NBLOCKS; k += NTHREADS)
            d += (double)g_partials[k];
        #pragma unroll
        for (int off = 16; off; off >>= 1)
            d += __shfl_xor_sync(0xffffffffu, d, off);

        __shared__ double sdw[NTHREADS / 32];
        if (lane == 0) sdw[wid] = d;
        __syncthreads();
        if (threadIdx.x == 0) {
            double total = 0.0;
            #pragma unroll
            for (int w = 0; w < NTHREADS / 32; w++) total += sdw[w];
            out[0] = (float)total;
            g_count = 0;                            // reset for next graph replay
        }
    }
}

extern "C" void kernel_launch(void* const* d_in, const int* in_sizes, int n_in,
                              void* d_out, int out_size) {
    const int*   ci    = (const int*)d_in[0];
    const int*   cj    = (const int*)d_in[1];
    const float* V     = (const float*)d_in[2];
    const float* U     = (const float*)d_in[3];
    const float* vb    = (const float*)d_in[4];
    const float* ub    = (const float*)d_in[5];
    const float* comat = (const float*)d_in[6];
    float* out = (float*)d_out;

    const int conv_items = 2 * VOCAB * H2_PER_ROW;  // 3M half2 writes
    glove_conv_kernel<<<(conv_items + 255) / 256, 256>>>(V, U);
    glove_main_kernel<<<NBLOCKS, NTHREADS>>>(ci, cj, vb, ub, comat, out);
}